// round 13
// baseline (speedup 1.0000x reference)
#include <cuda_runtime.h>
#include <cuda_fp16.h>
#include <cstdint>

#define V    8      // output rows per thread
#define XPT  4      // output cols per thread (two half2 pairs)
#define RIN  (V + 4)
#define WIMG 1024
#define HIMG 1024

__constant__ __half2 c_w2[25];        // packed (w,w) per tap — constant loads, 0 GPRs
__device__   __half2 g_w2_stage[25];  // staging (device-writable scratch)

__global__ void prep_weights(const float* __restrict__ filt)
{
    const int t = threadIdx.x;
    if (t < 25) g_w2_stage[t] = __floats2half2_rn(filt[t], filt[t]);
}

// (hi(a), lo(b)) from two half2's: bytes {a.b2,a.b3,b.b0,b.b1}.
__device__ __forceinline__ __half2 shift_pair(__half2 a, __half2 b)
{
    const uint32_t r = __byte_perm(*reinterpret_cast<uint32_t*>(&a),
                                   *reinterpret_cast<uint32_t*>(&b), 0x5432);
    return *reinterpret_cast<const __half2*>(&r);
}

__global__ __launch_bounds__(256, 5)
void erosion5x5_kernel(const float* __restrict__ img,
                       float* __restrict__ out)
{
    const int plane = blockIdx.y;                 // fused (b,c): 0..95
    const int y0    = blockIdx.x * V;             // output row base
    const int x0    = threadIdx.x * XPT;          // 0, 4, ..., 1020

    const float* p = img + (size_t)plane * HIMG * WIMG;
    float*       q = out + (size_t)plane * HIMG * WIMG + (size_t)y0 * WIMG + x0;

    const float   INF  = __int_as_float(0x7f800000);
    const __half2 INF2 = __floats2half2_rn(INF, INF);

    // Thread needs cols x0-2 .. x0+5.
    const bool leftEdge  = (x0 == 0);
    const bool rightEdge = (x0 + 4 >= WIMG);      // only x0==1020

    // Aligned center load (the only long-latency one -> pipelined).
    auto load_b = [&](int r) -> float4 {
        const int yy = y0 - 2 + r;
        if (yy >= 0 && yy < HIMG)
            return *reinterpret_cast<const float4*>(p + (size_t)yy * WIMG + x0);
        return make_float4(INF, INF, INF, INF);
    };

    // Accumulators: V rows x 2 column-pairs, fp16x2.
    __half2 acc[V][2];
#pragma unroll
    for (int o = 0; o < V; ++o) { acc[o][0] = INF2; acc[o][1] = INF2; }

    // Software pipeline on the center load only.
    float4 b_cur = load_b(0);

#pragma unroll
    for (int r = 0; r < RIN; ++r) {
        float4 b_nxt;
        if (r + 1 < RIN) b_nxt = load_b(r + 1);

        // Halo loads at consumption time: same 128B lines as neighbor lanes'
        // center loads -> L1 hits (~39 cyc), no pipelining needed.
        const int yy = y0 - 2 + r;
        const bool rowok = (yy >= 0 && yy < HIMG);
        float2 a, c2;
        if (rowok && !leftEdge)
            a = *reinterpret_cast<const float2*>(p + (size_t)yy * WIMG + x0 - 2);
        else
            a = make_float2(INF, INF);
        if (rowok && !rightEdge)
            c2 = *reinterpret_cast<const float2*>(p + (size_t)yy * WIMG + x0 + 4);
        else
            c2 = make_float2(INF, INF);

        // Pack current row: 4 cvt + 3 PRMT (bitwise = converting each pair).
        __half2 P[7];
        P[0] = __floats2half2_rn(a.x,     a.y);     // (s0,s1)
        P[2] = __floats2half2_rn(b_cur.x, b_cur.y); // (s2,s3)
        P[4] = __floats2half2_rn(b_cur.z, b_cur.w); // (s4,s5)
        P[6] = __floats2half2_rn(c2.x,    c2.y);    // (s6,s7)
        P[1] = shift_pair(P[0], P[2]);              // (s1,s2)
        P[3] = shift_pair(P[2], P[4]);              // (s3,s4)
        P[5] = shift_pair(P[4], P[6]);              // (s5,s6)

        // Input row r feeds output row o = r - i through filter row i.
#pragma unroll
        for (int i = 0; i < 5; ++i) {
            const int o = r - i;
            if (o < 0 || o >= V) continue;   // compile-time pruned
#pragma unroll
            for (int j = 0; j < 5; ++j) {
                const __half2 w = c_w2[i * 5 + j];   // constant load, 0 GPRs
                acc[o][0] = __hmin2(acc[o][0], __hsub2(P[j],     w));   // cols (0,1)
                acc[o][1] = __hmin2(acc[o][1], __hsub2(P[j + 2], w));   // cols (2,3)
            }
        }

        b_cur = b_nxt;
    }

#pragma unroll
    for (int o = 0; o < V; ++o) {
        const float2 lo = __half22float2(acc[o][0]);
        const float2 hi = __half22float2(acc[o][1]);
        float4 v = make_float4(lo.x, lo.y, hi.x, hi.y);
        *reinterpret_cast<float4*>(q + (size_t)o * WIMG) = v;   // STG.128
    }
}

extern "C" void kernel_launch(void* const* d_in, const int* in_sizes, int n_in,
                              void* d_out, int out_size)
{
    const float* img  = (const float*)d_in[0];
    const float* filt = (const float*)d_in[1];
    float*       out  = (float*)d_out;

    // 1) Convert filter -> packed half2 in device staging array.
    prep_weights<<<1, 32>>>(filt);

    // 2) Stage -> constant bank (D2D memcpy node; graph-capturable, no alloc).
    void* stage_ptr = nullptr;
    cudaGetSymbolAddress(&stage_ptr, g_w2_stage);
    cudaMemcpyToSymbolAsync(c_w2, stage_ptr, 25 * sizeof(__half2), 0,
                            cudaMemcpyDeviceToDevice, 0);

    const int planes = in_sizes[0] / (HIMG * WIMG);   // 32*3 = 96

    dim3 block(WIMG / XPT);          // 256 threads: one row-strip of the plane
    dim3 grid(HIMG / V, planes);     // (128, 96)
    erosion5x5_kernel<<<grid, block>>>(img, out);
}

// round 14
// speedup vs baseline: 1.0558x; 1.0558x over previous
#include <cuda_runtime.h>
#include <cuda_fp16.h>
#include <cstdint>

#define V    8      // output rows per thread
#define XPT  4      // output cols per thread (two half2 pairs)
#define RIN  (V + 4)
#define WIMG 1024
#define HIMG 1024
#define FULLMASK 0xffffffffu

__constant__ __half2 c_w2[25];        // packed (w,w) per tap — constant loads, 0 GPRs
__device__   __half2 g_w2_stage[25];  // staging (device-writable scratch)

__global__ void prep_weights(const float* __restrict__ filt)
{
    const int t = threadIdx.x;
    if (t < 25) g_w2_stage[t] = __floats2half2_rn(filt[t], filt[t]);
}

// (hi(a), lo(b)) from two half2's: bytes {a.b2,a.b3,b.b0,b.b1}.
__device__ __forceinline__ __half2 shift_pair(__half2 a, __half2 b)
{
    const uint32_t r = __byte_perm(*reinterpret_cast<uint32_t*>(&a),
                                   *reinterpret_cast<uint32_t*>(&b), 0x5432);
    return *reinterpret_cast<const __half2*>(&r);
}

__device__ __forceinline__ uint32_t h2bits(__half2 h) { return *reinterpret_cast<uint32_t*>(&h); }
__device__ __forceinline__ __half2  bits2h(uint32_t u){ return *reinterpret_cast<__half2*>(&u); }

__global__ __launch_bounds__(256, 5)
void erosion5x5_kernel(const float* __restrict__ img,
                       float* __restrict__ out)
{
    const int plane = blockIdx.y;                 // fused (b,c): 0..95
    const int y0    = blockIdx.x * V;             // output row base
    const int t     = threadIdx.x;
    const int x0    = t * XPT;                    // 0, 4, ..., 1020
    const int lane  = t & 31;

    const float* p = img + (size_t)plane * HIMG * WIMG;
    float*       q = out + (size_t)plane * HIMG * WIMG + (size_t)y0 * WIMG + x0;

    const float   INF  = __int_as_float(0x7f800000);
    const __half2 INF2 = __floats2half2_rn(INF, INF);

    const bool leftEdge  = (x0 == 0);             // only thread 0 of warp 0
    const bool rightEdge = (x0 + 4 >= WIMG);      // only x0==1020

    // Center load: 16B aligned, the only long-latency load (pipelined).
    auto load_b = [&](int r) -> float4 {
        const int yy = y0 - 2 + r;
        if (yy >= 0 && yy < HIMG)
            return *reinterpret_cast<const float4*>(p + (size_t)yy * WIMG + x0);
        return make_float4(INF, INF, INF, INF);
    };
    // Warp-boundary halo loads: only lanes 0 / 31 actually load (predicated).
    auto load_e0 = [&](int r) -> float2 {
        const int yy = y0 - 2 + r;
        if (lane == 0 && !leftEdge && yy >= 0 && yy < HIMG)
            return *reinterpret_cast<const float2*>(p + (size_t)yy * WIMG + x0 - 2);
        return make_float2(INF, INF);
    };
    auto load_e6 = [&](int r) -> float2 {
        const int yy = y0 - 2 + r;
        if (lane == 31 && !rightEdge && yy >= 0 && yy < HIMG)
            return *reinterpret_cast<const float2*>(p + (size_t)yy * WIMG + x0 + 4);
        return make_float2(INF, INF);
    };

    // Build even pairs Pc = {P0,P2,P4,P6} for one row from center + shuffles.
    auto pack = [&](float4 b, float2 e0, float2 e6, __half2 Pc[4]) {
        const __half2 Pb0 = __floats2half2_rn(b.x, b.y);   // (x0,   x0+1)
        const __half2 Pb1 = __floats2half2_rn(b.z, b.w);   // (x0+2, x0+3)
        const uint32_t up = __shfl_up_sync  (FULLMASK, h2bits(Pb1), 1); // lane-1's Pb1
        const uint32_t dn = __shfl_down_sync(FULLMASK, h2bits(Pb0), 1); // lane+1's Pb0
        const __half2 Pe0 = __floats2half2_rn(e0.x, e0.y);
        const __half2 Pe6 = __floats2half2_rn(e6.x, e6.y);
        Pc[0] = (lane == 0)  ? Pe0 : bits2h(up);           // (x0-2, x0-1)
        Pc[1] = Pb0;
        Pc[2] = Pb1;
        Pc[3] = (lane == 31) ? Pe6 : bits2h(dn);           // (x0+4, x0+5)
    };

    __half2 acc[V][2];
#pragma unroll
    for (int o = 0; o < V; ++o) { acc[o][0] = INF2; acc[o][1] = INF2; }

    // Prologue: pack row 0.
    __half2 Pc[4];
    {
        float4 b0 = load_b(0);
        float2 e0 = load_e0(0), e6 = load_e6(0);
        pack(b0, e0, e6, Pc);
    }

#pragma unroll
    for (int r = 0; r < RIN; ++r) {
        // Issue next row's loads before this row's math (proven R12 shape).
        float4 b_n;  float2 e0_n, e6_n;
        if (r + 1 < RIN) {
            b_n  = load_b(r + 1);
            e0_n = load_e0(r + 1);
            e6_n = load_e6(r + 1);
        }

        // Full 7-pair window: odd pairs derived by byte-permute (bitwise = cvt).
        __half2 Pf[7];
        Pf[0] = Pc[0];
        Pf[2] = Pc[1];
        Pf[4] = Pc[2];
        Pf[6] = Pc[3];
        Pf[1] = shift_pair(Pf[0], Pf[2]);
        Pf[3] = shift_pair(Pf[2], Pf[4]);
        Pf[5] = shift_pair(Pf[4], Pf[6]);

        // Input row r feeds output row o = r - i through filter row i.
#pragma unroll
        for (int i = 0; i < 5; ++i) {
            const int o = r - i;
            if (o < 0 || o >= V) continue;   // compile-time pruned
#pragma unroll
            for (int j = 0; j < 5; ++j) {
                const __half2 w = c_w2[i * 5 + j];   // constant load, 0 GPRs
                acc[o][0] = __hmin2(acc[o][0], __hsub2(Pf[j],     w));   // cols (0,1)
                acc[o][1] = __hmin2(acc[o][1], __hsub2(Pf[j + 2], w));   // cols (2,3)
            }
        }

        // Convert/exchange next row after the math (load latency fully covered).
        if (r + 1 < RIN) pack(b_n, e0_n, e6_n, Pc);
    }

#pragma unroll
    for (int o = 0; o < V; ++o) {
        const float2 lo = __half22float2(acc[o][0]);
        const float2 hi = __half22float2(acc[o][1]);
        float4 v = make_float4(lo.x, lo.y, hi.x, hi.y);
        *reinterpret_cast<float4*>(q + (size_t)o * WIMG) = v;   // STG.128
    }
}

extern "C" void kernel_launch(void* const* d_in, const int* in_sizes, int n_in,
                              void* d_out, int out_size)
{
    const float* img  = (const float*)d_in[0];
    const float* filt = (const float*)d_in[1];
    float*       out  = (float*)d_out;

    // 1) Convert filter -> packed half2 in device staging array.
    prep_weights<<<1, 32>>>(filt);

    // 2) Stage -> constant bank (D2D memcpy node; graph-capturable, no alloc).
    void* stage_ptr = nullptr;
    cudaGetSymbolAddress(&stage_ptr, g_w2_stage);
    cudaMemcpyToSymbolAsync(c_w2, stage_ptr, 25 * sizeof(__half2), 0,
                            cudaMemcpyDeviceToDevice, 0);

    const int planes = in_sizes[0] / (HIMG * WIMG);   // 32*3 = 96

    dim3 block(WIMG / XPT);          // 256 threads: one row-strip of the plane
    dim3 grid(HIMG / V, planes);     // (128, 96)
    erosion5x5_kernel<<<grid, block>>>(img, out);
}

// round 15
// speedup vs baseline: 1.5067x; 1.4270x over previous
#include <cuda_runtime.h>
#include <cuda_fp16.h>
#include <cstdint>

#define V    8      // output rows per thread
#define XPT  4      // output cols per thread (two half2 pairs)
#define RIN  (V + 4)
#define WIMG 1024
#define HIMG 1024

__constant__ __half2 c_w2[25];        // packed (w,w) per tap — constant loads, 0 GPRs
__device__   __half2 g_w2_stage[25];  // staging (device-writable scratch)

__global__ void prep_weights(const float* __restrict__ filt)
{
    const int t = threadIdx.x;
    if (t < 25) g_w2_stage[t] = __floats2half2_rn(filt[t], filt[t]);
}

// (hi(a), lo(b)) from two half2's: bytes {a.b2,a.b3,b.b0,b.b1}.
__device__ __forceinline__ __half2 shift_pair(__half2 a, __half2 b)
{
    const uint32_t r = __byte_perm(*reinterpret_cast<uint32_t*>(&a),
                                   *reinterpret_cast<uint32_t*>(&b), 0x5432);
    return *reinterpret_cast<const __half2*>(&r);
}

__global__ __launch_bounds__(256, 4)
void erosion5x5_kernel(const float* __restrict__ img,
                       float* __restrict__ out)
{
    const int plane = blockIdx.y;                 // fused (b,c): 0..95
    const int y0    = blockIdx.x * V;             // output row base
    const int x0    = threadIdx.x * XPT;          // 0, 4, ..., 1020

    const float* p = img + (size_t)plane * HIMG * WIMG;
    float*       q = out + (size_t)plane * HIMG * WIMG + (size_t)y0 * WIMG + x0;

    const float   INF  = __int_as_float(0x7f800000);
    const __half2 INF2 = __floats2half2_rn(INF, INF);

    // Thread needs cols x0-2 .. x0+5.
    const bool leftEdge  = (x0 == 0);
    const bool rightEdge = (x0 + 4 >= WIMG);      // only x0==1020

    // Center load: 16B-aligned, the long-latency stream (pipelined, distance 2).
    auto load_b = [&](int r) -> float4 {
        const int yy = y0 - 2 + r;
        if (yy >= 0 && yy < HIMG)
            return *reinterpret_cast<const float4*>(p + (size_t)yy * WIMG + x0);
        return make_float4(INF, INF, INF, INF);
    };

    // Accumulators: V rows x 2 column-pairs, fp16x2.
    __half2 acc[V][2];
#pragma unroll
    for (int o = 0; o < V; ++o) { acc[o][0] = INF2; acc[o][1] = INF2; }

    // Prologue: center loads for rows 0 and 1 in flight.
    float4 b_cur = load_b(0);
    float4 b_n1  = load_b(1);

#pragma unroll
    for (int r = 0; r < RIN; ++r) {
        // 1) Deepest prefetch first: center load for row r+2.
        float4 b_n2;
        if (r + 2 < RIN) b_n2 = load_b(r + 2);

        // 2) Halo loads for the CURRENT row: their 128B lines were fetched by
        //    this warp's own center loads two iterations ago -> L1 hits.
        //    Branch-form, unconditional inside rowok (the non-spilling shape).
        const int yy = y0 - 2 + r;
        float2 a, c2;
        if (yy >= 0 && yy < HIMG) {
            const float* row = p + (size_t)yy * WIMG + x0;
            a  = leftEdge  ? make_float2(INF, INF)
                           : *reinterpret_cast<const float2*>(row - 2);
            c2 = rightEdge ? make_float2(INF, INF)
                           : *reinterpret_cast<const float2*>(row + 4);
        } else {
            a  = make_float2(INF, INF);
            c2 = make_float2(INF, INF);
        }

        // 3) Pack current row: 4 cvt + 3 PRMT (bitwise = converting each pair).
        __half2 P[7];
        P[0] = __floats2half2_rn(a.x,     a.y);     // (s0,s1)
        P[2] = __floats2half2_rn(b_cur.x, b_cur.y); // (s2,s3)
        P[4] = __floats2half2_rn(b_cur.z, b_cur.w); // (s4,s5)
        P[6] = __floats2half2_rn(c2.x,    c2.y);    // (s6,s7)
        P[1] = shift_pair(P[0], P[2]);              // (s1,s2)
        P[3] = shift_pair(P[2], P[4]);              // (s3,s4)
        P[5] = shift_pair(P[4], P[6]);              // (s5,s6)

        // 4) Math: input row r feeds output row o = r - i through filter row i.
#pragma unroll
        for (int i = 0; i < 5; ++i) {
            const int o = r - i;
            if (o < 0 || o >= V) continue;   // compile-time pruned
#pragma unroll
            for (int j = 0; j < 5; ++j) {
                const __half2 w = c_w2[i * 5 + j];   // constant load, 0 GPRs
                acc[o][0] = __hmin2(acc[o][0], __hsub2(P[j],     w));   // cols (0,1)
                acc[o][1] = __hmin2(acc[o][1], __hsub2(P[j + 2], w));   // cols (2,3)
            }
        }

        // 5) Rotate the center-load pipeline.
        b_cur = b_n1;
        b_n1  = b_n2;
    }

#pragma unroll
    for (int o = 0; o < V; ++o) {
        const float2 lo = __half22float2(acc[o][0]);
        const float2 hi = __half22float2(acc[o][1]);
        float4 v = make_float4(lo.x, lo.y, hi.x, hi.y);
        *reinterpret_cast<float4*>(q + (size_t)o * WIMG) = v;   // STG.128
    }
}

extern "C" void kernel_launch(void* const* d_in, const int* in_sizes, int n_in,
                              void* d_out, int out_size)
{
    const float* img  = (const float*)d_in[0];
    const float* filt = (const float*)d_in[1];
    float*       out  = (float*)d_out;

    // 1) Convert filter -> packed half2 in device staging array.
    prep_weights<<<1, 32>>>(filt);

    // 2) Stage -> constant bank (D2D memcpy node; graph-capturable, no alloc).
    void* stage_ptr = nullptr;
    cudaGetSymbolAddress(&stage_ptr, g_w2_stage);
    cudaMemcpyToSymbolAsync(c_w2, stage_ptr, 25 * sizeof(__half2), 0,
                            cudaMemcpyDeviceToDevice, 0);

    const int planes = in_sizes[0] / (HIMG * WIMG);   // 32*3 = 96

    dim3 block(WIMG / XPT);          // 256 threads: one row-strip of the plane
    dim3 grid(HIMG / V, planes);     // (128, 96)
    erosion5x5_kernel<<<grid, block>>>(img, out);
}

// round 16
// speedup vs baseline: 1.7876x; 1.1864x over previous
#include <cuda_runtime.h>
#include <cuda_fp16.h>
#include <cstdint>

#define V    16     // output rows per thread (rolling 5-slot accumulator ring)
#define XPT  4      // output cols per thread (two half2 pairs)
#define RIN  (V + 4)
#define WIMG 1024
#define HIMG 1024

__constant__ __half2 c_w2[25];        // packed (w,w) per tap — constant loads, 0 GPRs
__device__   __half2 g_w2_stage[25];  // staging (device-writable scratch)

__global__ void prep_weights(const float* __restrict__ filt)
{
    const int t = threadIdx.x;
    if (t < 25) g_w2_stage[t] = __floats2half2_rn(filt[t], filt[t]);
}

// (hi(a), lo(b)) from two half2's: bytes {a.b2,a.b3,b.b0,b.b1}.
__device__ __forceinline__ __half2 shift_pair(__half2 a, __half2 b)
{
    const uint32_t r = __byte_perm(*reinterpret_cast<uint32_t*>(&a),
                                   *reinterpret_cast<uint32_t*>(&b), 0x5432);
    return *reinterpret_cast<const __half2*>(&r);
}

__global__ __launch_bounds__(256, 4)
void erosion5x5_kernel(const float* __restrict__ img,
                       float* __restrict__ out)
{
    const int plane = blockIdx.y;                 // fused (b,c): 0..95
    const int y0    = blockIdx.x * V;             // output row base
    const int x0    = threadIdx.x * XPT;          // 0, 4, ..., 1020

    const float* p = img + (size_t)plane * HIMG * WIMG;
    float*       q = out + (size_t)plane * HIMG * WIMG + (size_t)y0 * WIMG + x0;

    const float   INF  = __int_as_float(0x7f800000);
    const __half2 INF2 = __floats2half2_rn(INF, INF);

    // Thread needs cols x0-2 .. x0+5.
    const bool leftEdge  = (x0 == 0);
    const bool rightEdge = (x0 + 4 >= WIMG);      // only x0==1020

    // R12's proven row loader: all three loads under one branch, batched.
    auto load_row = [&](int r, float2& a, float4& b, float2& c2) {
        const int yy = y0 - 2 + r;
        if (yy >= 0 && yy < HIMG) {
            const float* row = p + (size_t)yy * WIMG + x0;
            a  = leftEdge  ? make_float2(INF, INF)
                           : *reinterpret_cast<const float2*>(row - 2);
            b  = *reinterpret_cast<const float4*>(row);
            c2 = rightEdge ? make_float2(INF, INF)
                           : *reinterpret_cast<const float2*>(row + 4);
        } else {
            a  = make_float2(INF, INF);
            b  = make_float4(INF, INF, INF, INF);
            c2 = make_float2(INF, INF);
        }
    };

    // Rolling accumulator ring: at input row r only outputs r-4..r are live.
    __half2 acc[5][2];
#pragma unroll
    for (int s = 0; s < 5; ++s) { acc[s][0] = INF2; acc[s][1] = INF2; }

    // Software pipeline (distance 1, R12 shape).
    float2 a_cur, c_cur;  float4 b_cur;
    load_row(0, a_cur, b_cur, c_cur);

#pragma unroll
    for (int r = 0; r < RIN; ++r) {
        float2 a_nxt, c_nxt;  float4 b_nxt;
        if (r + 1 < RIN) load_row(r + 1, a_nxt, b_nxt, c_nxt);

        // Pack current row: 4 cvt + 3 PRMT (bitwise = converting each pair).
        __half2 P[7];
        P[0] = __floats2half2_rn(a_cur.x, a_cur.y);   // (s0,s1)
        P[2] = __floats2half2_rn(b_cur.x, b_cur.y);   // (s2,s3)
        P[4] = __floats2half2_rn(b_cur.z, b_cur.w);   // (s4,s5)
        P[6] = __floats2half2_rn(c_cur.x, c_cur.y);   // (s6,s7)
        P[1] = shift_pair(P[0], P[2]);                // (s1,s2)
        P[3] = shift_pair(P[2], P[4]);                // (s3,s4)
        P[5] = shift_pair(P[4], P[6]);                // (s5,s6)

        // Input row r feeds output row o = r - i through filter row i.
#pragma unroll
        for (int i = 0; i < 5; ++i) {
            const int o = r - i;
            if (o < 0 || o >= V) continue;     // compile-time pruned
            const int s = o % 5;               // compile-time constant slot
#pragma unroll
            for (int j = 0; j < 5; ++j) {
                const __half2 w = c_w2[i * 5 + j];   // constant load, 0 GPRs
                acc[s][0] = __hmin2(acc[s][0], __hsub2(P[j],     w));   // cols (0,1)
                acc[s][1] = __hmin2(acc[s][1], __hsub2(P[j + 2], w));   // cols (2,3)
            }
        }

        // Output row r-4 is complete: store it, recycle its ring slot.
        if (r >= 4) {
            const int o = r - 4;               // 0..V-1, compile-time
            const int s = o % 5;
            const float2 lo = __half22float2(acc[s][0]);
            const float2 hi = __half22float2(acc[s][1]);
            float4 v = make_float4(lo.x, lo.y, hi.x, hi.y);
            *reinterpret_cast<float4*>(q + (size_t)o * WIMG) = v;   // STG.128
            acc[s][0] = INF2;  acc[s][1] = INF2;   // ready for output row o+5
        }

        a_cur = a_nxt;  b_cur = b_nxt;  c_cur = c_nxt;
    }
}

extern "C" void kernel_launch(void* const* d_in, const int* in_sizes, int n_in,
                              void* d_out, int out_size)
{
    const float* img  = (const float*)d_in[0];
    const float* filt = (const float*)d_in[1];
    float*       out  = (float*)d_out;

    // 1) Convert filter -> packed half2 in device staging array.
    prep_weights<<<1, 32>>>(filt);

    // 2) Stage -> constant bank (D2D memcpy node; graph-capturable, no alloc).
    void* stage_ptr = nullptr;
    cudaGetSymbolAddress(&stage_ptr, g_w2_stage);
    cudaMemcpyToSymbolAsync(c_w2, stage_ptr, 25 * sizeof(__half2), 0,
                            cudaMemcpyDeviceToDevice, 0);

    const int planes = in_sizes[0] / (HIMG * WIMG);   // 32*3 = 96

    dim3 block(WIMG / XPT);          // 256 threads: one row-strip of the plane
    dim3 grid(HIMG / V, planes);     // (64, 96)
    erosion5x5_kernel<<<grid, block>>>(img, out);
}